// round 9
// baseline (speedup 1.0000x reference)
#include <cuda_runtime.h>

// image [1,128,128,512] f32 NHWC, RoI [N,4] f32 (cx,cy,w,h), POOL=7, STRIDE=16.
#define POOL    7
#define HH      128
#define WW      128
#define CC      512
#define NMAX    1024
#define MAXCELL (NMAX * POOL * POOL)

// Per-cell params (allocation-free rule: __device__ globals).
__device__ int4   g_off[MAXCELL];   // 4 corner offsets, float4 units
__device__ float4 g_w  [MAXCELL];   // 4 bilinear weights

// ---------------------------------------------------------------------------
// Kernel 1: one thread per (roi, py, px) cell -> corner offsets + weights.
// Matches reference math exactly (rintf = round-half-even, floor, clip order).
// ---------------------------------------------------------------------------
__global__ void roi_prep_kernel(const float* __restrict__ roi, int totalCells)
{
    int cell = blockIdx.x * blockDim.x + threadIdx.x;
    if (cell >= totalCells) return;

    int n   = cell / (POOL * POOL);
    int rem = cell - n * (POOL * POOL);
    int py  = rem / POOL;
    int px  = rem - py * POOL;

    const float inv_stride = 1.0f / 16.0f;
    float cx = roi[n * 4 + 0];
    float cy = roi[n * 4 + 1];
    float w  = roi[n * 4 + 2];
    float h  = roi[n * 4 + 3];

    float r  = rintf((cx - 0.5f * w) * inv_stride);   // x start (col)
    float c  = rintf((cy - 0.5f * h) * inv_stride);   // y start (row)
    float wq = fmaxf(rintf(w * inv_stride), 1.0f);
    float hq = fmaxf(rintf(h * inv_stride), 1.0f);

    // y axis (rows, limit HH)
    float gy  = (py + 0.5f) / (float)POOL;
    float sy  = fminf(fmaxf(gy * hq - 0.5f, 0.0f), hq - 1.0f);
    float fy0 = floorf(sy);
    float ly  = sy - fy0;
    float fy1 = fminf(fy0 + 1.0f, hq - 1.0f);
    int iy0 = (int)fminf(fmaxf(c + fy0, 0.0f), (float)(HH - 1));
    int iy1 = (int)fminf(fmaxf(c + fy1, 0.0f), (float)(HH - 1));

    // x axis (cols, limit WW)
    float gx  = (px + 0.5f) / (float)POOL;
    float sx  = fminf(fmaxf(gx * wq - 0.5f, 0.0f), wq - 1.0f);
    float fx0 = floorf(sx);
    float lx  = sx - fx0;
    float fx1 = fminf(fx0 + 1.0f, wq - 1.0f);
    int ix0 = (int)fminf(fmaxf(r + fx0, 0.0f), (float)(WW - 1));
    int ix1 = (int)fminf(fmaxf(r + fx1, 0.0f), (float)(WW - 1));

    g_off[cell] = make_int4((iy0 * WW + ix0) * (CC / 4),
                            (iy0 * WW + ix1) * (CC / 4),
                            (iy1 * WW + ix0) * (CC / 4),
                            (iy1 * WW + ix1) * (CC / 4));
    g_w[cell] = make_float4((1.0f - ly) * (1.0f - lx),
                            (1.0f - ly) * lx,
                            ly * (1.0f - lx),
                            ly * lx);
}

// ---------------------------------------------------------------------------
// Kernel 2: PERSISTENT grid-stride kernel. One wave (148x6 CTAs, 48 warps/SM
// resident for the whole kernel): no wave transitions, no CTA ramp/drain,
// steady uniform feed of the L1tex queue instead of front-batched bursts.
// 128 threads per cell (each thread: 1 float4 lane x 4 corners, MLP=4).
// Next cell's params are prefetched at the top of each iteration so the
// param->data dependent chain is hidden by the previous data phase.
// ---------------------------------------------------------------------------
__global__ __launch_bounds__(256, 6)
void roi_pool_kernel(const float* __restrict__ img, float* __restrict__ out,
                     int totalCells)
{
    const int lane   = threadIdx.x & 127;          // float4 lane within cell
    const int sub    = threadIdx.x >> 7;           // 0/1: cell slot in CTA
    const int stride = gridDim.x * 2;              // cells per full sweep

    const float4* __restrict__ img4 = (const float4*)img;
    float4*       __restrict__ out4 = (float4*)out;

    int cell = blockIdx.x * 2 + sub;
    if (cell >= totalCells) return;

    // Prime the pipeline: params for first cell.
    int4   o = g_off[cell];
    float4 w = g_w[cell];

    while (true) {
        int next = cell + stride;

        // Prefetch next cell's params (independent of this iteration's data).
        int4   o_n = o;
        float4 w_n = w;
        if (next < totalCells) {
            o_n = g_off[next];
            w_n = g_w[next];
        }

        // 4 independent corner loads for this cell.
        float4 a = __ldg(img4 + o.x + lane);
        float4 b = __ldg(img4 + o.y + lane);
        float4 c = __ldg(img4 + o.z + lane);
        float4 d = __ldg(img4 + o.w + lane);

        float4 r;
        r.x = w.x * a.x + w.y * b.x + w.z * c.x + w.w * d.x;
        r.y = w.x * a.y + w.y * b.y + w.z * c.y + w.w * d.y;
        r.z = w.x * a.z + w.y * b.z + w.z * c.z + w.w * d.z;
        r.w = w.x * a.w + w.y * b.w + w.z * c.w + w.w * d.w;

        __stcs(out4 + (size_t)cell * (CC / 4) + lane, r);

        if (next >= totalCells) break;
        cell = next;
        o = o_n;
        w = w_n;
    }
}

extern "C" void kernel_launch(void* const* d_in, const int* in_sizes, int n_in,
                              void* d_out, int out_size)
{
    const float* img = (const float*)d_in[0];   // [1,128,128,512] f32
    const float* roi = (const float*)d_in[1];   // [N,4] f32
    float*       out = (float*)d_out;           // [1,N,7,7,512] f32

    int N = in_sizes[1] / 4;
    if (N > NMAX) N = NMAX;
    int totalCells = N * POOL * POOL;

    roi_prep_kernel<<<(totalCells + 255) / 256, 256>>>(roi, totalCells);

    int grid = 148 * 6;                          // one persistent wave
    int maxCtas = (totalCells + 1) / 2;          // never launch idle CTAs
    if (grid > maxCtas) grid = maxCtas;
    roi_pool_kernel<<<grid, 256>>>(img, out, totalCells);
}